// round 1
// baseline (speedup 1.0000x reference)
#include <cuda_runtime.h>
#include <cstdint>

#define BATCH 2
#define SEQ   2048
#define DIMN  768
#define NH    12
#define HD    64

#define TQ 16
#define TK 32
#define QS_STRIDE (DIMN + 4)   /* 772: stride-4 mod 32 banks -> conflict-free row accesses */
#define P_STRIDE  (TK + 1)     /* 33 */

// Scratch for Q/K/V projections (allocation-free rule: __device__ globals)
__device__ float g_Q[BATCH * SEQ * DIMN];
__device__ float g_K[BATCH * SEQ * DIMN];
__device__ float g_V[BATCH * SEQ * DIMN];

// ---------------------------------------------------------------------------
// fast exp on the FMA pipe (avoids MUFU bottleneck: 100M exps in this problem).
// e^s = 2^r * exp(g), g = (s*log2e - r)*ln2, |g| <= 0.3466, deg-6 Taylor,
// relative error ~1e-8. Clamp keeps the exponent bit-trick in range.
// ---------------------------------------------------------------------------
__device__ __forceinline__ float fast_exp(float s) {
    float t = s * 1.4426950408889634f;
    t = fminf(fmaxf(t, -120.0f), 120.0f);
    float r = rintf(t);
    float g = (t - r) * 0.69314718055994531f;
    float p = 1.3888889e-3f;
    p = fmaf(p, g, 8.3333333e-3f);
    p = fmaf(p, g, 4.1666667e-2f);
    p = fmaf(p, g, 1.6666667e-1f);
    p = fmaf(p, g, 0.5f);
    p = fmaf(p, g, 1.0f);
    p = fmaf(p, g, 1.0f);
    int ri = (int)r;
    return p * __int_as_float((ri + 127) << 23);
}

// ---------------------------------------------------------------------------
// Kernel 1: QKV projection. Y = X @ W^T  (NT SGEMM).
// X: (4096, 768) row-major. W: (768, 768) row-major (row j = output feature j).
// 128x128 block tile, BK=16, 8x8 per-thread microtile, 256 threads.
// grid = (32, 6, 3); z selects Wq/Wk/Wv -> g_Q/g_K/g_V.
// ---------------------------------------------------------------------------
__global__ __launch_bounds__(256) void qkv_gemm(
    const float* __restrict__ X,
    const float* __restrict__ Wq,
    const float* __restrict__ Wk,
    const float* __restrict__ Wv)
{
    __shared__ float As[16][132];
    __shared__ float Bs[16][132];

    const float* W;
    float* Y;
    if (blockIdx.z == 0)      { W = Wq; Y = g_Q; }
    else if (blockIdx.z == 1) { W = Wk; Y = g_K; }
    else                      { W = Wv; Y = g_V; }

    const int tid = threadIdx.x;
    const int tx  = tid & 15;
    const int ty  = tid >> 4;
    const int bm  = blockIdx.x * 128;
    const int bn  = blockIdx.y * 128;

    float acc[8][8];
#pragma unroll
    for (int i = 0; i < 8; i++)
#pragma unroll
        for (int j = 0; j < 8; j++) acc[i][j] = 0.0f;

    for (int k0 = 0; k0 < DIMN; k0 += 16) {
#pragma unroll
        for (int i = 0; i < 2; i++) {
            int s   = tid + 256 * i;       // 0..511 float4 slots
            int row = s >> 2;              // 0..127
            int c4  = (s & 3) << 2;        // 0,4,8,12
            float4 va = *(const float4*)(X + (size_t)(bm + row) * DIMN + k0 + c4);
            As[c4 + 0][row] = va.x; As[c4 + 1][row] = va.y;
            As[c4 + 2][row] = va.z; As[c4 + 3][row] = va.w;
            float4 vb = *(const float4*)(W + (size_t)(bn + row) * DIMN + k0 + c4);
            Bs[c4 + 0][row] = vb.x; Bs[c4 + 1][row] = vb.y;
            Bs[c4 + 2][row] = vb.z; Bs[c4 + 3][row] = vb.w;
        }
        __syncthreads();

#pragma unroll
        for (int kk = 0; kk < 16; kk++) {
            float a[8], bf[8];
            float4 a0 = *(const float4*)&As[kk][ty * 8];
            float4 a1 = *(const float4*)&As[kk][ty * 8 + 4];
            a[0] = a0.x; a[1] = a0.y; a[2] = a0.z; a[3] = a0.w;
            a[4] = a1.x; a[5] = a1.y; a[6] = a1.z; a[7] = a1.w;
#pragma unroll
            for (int j = 0; j < 8; j++) bf[j] = Bs[kk][tx + 16 * j];  // stride-16 cols: conflict-free
#pragma unroll
            for (int i = 0; i < 8; i++)
#pragma unroll
                for (int j = 0; j < 8; j++)
                    acc[i][j] = fmaf(a[i], bf[j], acc[i][j]);
        }
        __syncthreads();
    }

#pragma unroll
    for (int i = 0; i < 8; i++) {
        int row = bm + ty * 8 + i;
#pragma unroll
        for (int j = 0; j < 8; j++)
            Y[(size_t)row * DIMN + bn + tx + 16 * j] = acc[i][j];
    }
}

// ---------------------------------------------------------------------------
// Kernel 2: fused scores + head-axis softmax + AV.
// Block: 384 threads = 12 warps, warp w <-> head w. TQ=16 queries, TK=32 keys
// per tile streamed over SEQ. Softmax over the 12 heads is LOCAL per (q,k)
// cell -> no running max / rescale over k. One smem buffer reused for K then V.
// ---------------------------------------------------------------------------
__global__ __launch_bounds__(384, 1) void attn_kernel(float* __restrict__ Out)
{
    extern __shared__ float sm[];
    float* Qs = sm;                          // TQ * QS_STRIDE
    float* KV = Qs + TQ * QS_STRIDE;         // TK * QS_STRIDE (K, then V)
    float* P  = KV + TK * QS_STRIDE;         // NH * TQ * P_STRIDE

    const int tid  = threadIdx.x;
    const int w    = tid >> 5;               // head
    const int lane = tid & 31;
    const int hi2  = lane >> 3;              // 0..3  (q group)
    const int lo3  = lane & 7;               // 0..7  (k group in scores, d group in AV)

    const int b  = blockIdx.y;
    const int q0 = blockIdx.x * TQ;

    const float* Qg = g_Q + (size_t)(b * SEQ + q0) * DIMN;
    const float* Kg = g_K + (size_t)b * SEQ * DIMN;
    const float* Vg = g_V + (size_t)b * SEQ * DIMN;

    // Load Q tile (TQ x 768) once: 3072 float4 / 384 threads = 8 each.
#pragma unroll
    for (int i = 0; i < 8; i++) {
        int s   = tid + 384 * i;
        int row = s / 192;
        int c4  = (s % 192) * 4;
        float4 v = *(const float4*)(Qg + (size_t)row * DIMN + c4);
        *(float4*)(Qs + row * QS_STRIDE + c4) = v;
    }

    float oacc[4][8];
#pragma unroll
    for (int i = 0; i < 4; i++)
#pragma unroll
        for (int j = 0; j < 8; j++) oacc[i][j] = 0.0f;

    const float SCALE = 0.03608439182435161f;   // 1/sqrt(768)
    float* Pw = P + w * (TQ * P_STRIDE);

#pragma unroll 1
    for (int kt = 0; kt < SEQ; kt += TK) {
        __syncthreads();   // prev AV done: KV + P reusable (also guards Qs on iter 0)

        // --- load K tile: 6144 float4 / 384 threads = 16 each ---
#pragma unroll
        for (int i = 0; i < 16; i++) {
            int s   = tid + 384 * i;
            int row = s / 192;
            int c4  = (s % 192) * 4;
            float4 v = *(const float4*)(Kg + (size_t)(kt + row) * DIMN + c4);
            *(float4*)(KV + row * QS_STRIDE + c4) = v;
        }
        __syncthreads();

        // --- scores: warp w computes S_w (16q x 32k), 4q x 4k per lane ---
        {
            float sacc[4][4];
#pragma unroll
            for (int i = 0; i < 4; i++)
#pragma unroll
                for (int j = 0; j < 4; j++) sacc[i][j] = 0.0f;

            const float* Qb = Qs + w * HD;
            const float* Kb = KV + w * HD;
#pragma unroll
            for (int d4 = 0; d4 < 16; d4++) {
                float4 qv[4], kv[4];
#pragma unroll
                for (int i = 0; i < 4; i++)
                    qv[i] = *(const float4*)(Qb + (hi2 + 4 * i) * QS_STRIDE + d4 * 4);
#pragma unroll
                for (int j = 0; j < 4; j++)
                    kv[j] = *(const float4*)(Kb + (lo3 + 8 * j) * QS_STRIDE + d4 * 4);
#pragma unroll
                for (int i = 0; i < 4; i++)
#pragma unroll
                    for (int j = 0; j < 4; j++) {
                        sacc[i][j] = fmaf(qv[i].x, kv[j].x, sacc[i][j]);
                        sacc[i][j] = fmaf(qv[i].y, kv[j].y, sacc[i][j]);
                        sacc[i][j] = fmaf(qv[i].z, kv[j].z, sacc[i][j]);
                        sacc[i][j] = fmaf(qv[i].w, kv[j].w, sacc[i][j]);
                    }
            }
            // exp (poly, FMA pipe) and stage to smem
#pragma unroll
            for (int i = 0; i < 4; i++)
#pragma unroll
                for (int j = 0; j < 4; j++)
                    Pw[(hi2 + 4 * i) * P_STRIDE + (lo3 + 8 * j)] = fast_exp(sacc[i][j]);
        }
        __syncthreads();

        // --- load V tile into KV (K is dead) + normalize P across heads ---
#pragma unroll
        for (int i = 0; i < 16; i++) {
            int s   = tid + 384 * i;
            int row = s / 192;
            int c4  = (s % 192) * 4;
            float4 v = *(const float4*)(Vg + (size_t)(kt + row) * DIMN + c4);
            *(float4*)(KV + row * QS_STRIDE + c4) = v;
        }
        // head-axis softmax: each (q,k) cell owned by exactly one thread
#pragma unroll 1
        for (int c = tid; c < TQ * TK; c += 384) {
            int q = c >> 5;
            int k = c & 31;
            float e[NH];
            float den = 0.0f;
#pragma unroll
            for (int h = 0; h < NH; h++) {
                e[h] = P[h * (TQ * P_STRIDE) + q * P_STRIDE + k];
                den += e[h];
            }
            float sc = __fdividef(SCALE, den);
#pragma unroll
            for (int h = 0; h < NH; h++)
                P[h * (TQ * P_STRIDE) + q * P_STRIDE + k] = e[h] * sc;
        }
        __syncthreads();

        // --- AV: out(16q x 64d per head) += P_w(16x32) @ V_w(32x64) ---
        {
            const float* Vb0 = KV + w * HD + lo3 * 4;
#pragma unroll
            for (int kk = 0; kk < TK; kk++) {
                float pv[4];
#pragma unroll
                for (int i = 0; i < 4; i++)
                    pv[i] = Pw[(hi2 + 4 * i) * P_STRIDE + kk];
                const float* Vb = Vb0 + kk * QS_STRIDE;
                float4 v0 = *(const float4*)(Vb);        // d = lo3*4 .. +3
                float4 v1 = *(const float4*)(Vb + 32);   // d = 32 + lo3*4 .. +3
#pragma unroll
                for (int i = 0; i < 4; i++) {
                    oacc[i][0] = fmaf(pv[i], v0.x, oacc[i][0]);
                    oacc[i][1] = fmaf(pv[i], v0.y, oacc[i][1]);
                    oacc[i][2] = fmaf(pv[i], v0.z, oacc[i][2]);
                    oacc[i][3] = fmaf(pv[i], v0.w, oacc[i][3]);
                    oacc[i][4] = fmaf(pv[i], v1.x, oacc[i][4]);
                    oacc[i][5] = fmaf(pv[i], v1.y, oacc[i][5]);
                    oacc[i][6] = fmaf(pv[i], v1.z, oacc[i][6]);
                    oacc[i][7] = fmaf(pv[i], v1.w, oacc[i][7]);
                }
            }
        }
    }

    // --- write out: Out[(b*SEQ + q)*768 + w*64 + d] ---
    float* Ob = Out + (size_t)(b * SEQ + q0) * DIMN + w * HD;
#pragma unroll
    for (int i = 0; i < 4; i++) {
        int q = hi2 + 4 * i;
        *(float4*)(Ob + (size_t)q * DIMN + lo3 * 4) =
            make_float4(oacc[i][0], oacc[i][1], oacc[i][2], oacc[i][3]);
        *(float4*)(Ob + (size_t)q * DIMN + 32 + lo3 * 4) =
            make_float4(oacc[i][4], oacc[i][5], oacc[i][6], oacc[i][7]);
    }
}

// ---------------------------------------------------------------------------
extern "C" void kernel_launch(void* const* d_in, const int* in_sizes, int n_in,
                              void* d_out, int out_size)
{
    const float* x  = (const float*)d_in[0];
    const float* Wq = (const float*)d_in[1];
    const float* Wk = (const float*)d_in[2];
    const float* Wv = (const float*)d_in[3];
    float* out = (float*)d_out;

    dim3 g1(4096 / 128, DIMN / 128, 3);
    qkv_gemm<<<g1, 256>>>(x, Wq, Wk, Wv);

    size_t smem = (size_t)((TQ + TK) * QS_STRIDE + NH * TQ * P_STRIDE) * sizeof(float);
    cudaFuncSetAttribute(attn_kernel, cudaFuncAttributeMaxDynamicSharedMemorySize, (int)smem);
    dim3 g2(SEQ / TQ, BATCH);
    attn_kernel<<<g2, 384, smem>>>(out);
}

// round 4
// speedup vs baseline: 1.3996x; 1.3996x over previous
#include <cuda_runtime.h>
#include <cuda_bf16.h>
#include <cstdint>

#define BATCH 2
#define SEQ   2048
#define DIMN  768
#define NH    12
#define HD    64

#define TQ 32
#define TK 32

#define KSTR 776           /* 768 + 8 bf16 pad: row stride 1552B = 16 mod 128 -> ldmatrix conflict-free */
#define PST  33            /* fp32 P row stride */
#define PBST 40            /* bf16 P row stride: 80B stride -> distinct 16B groups mod 128 */

// split-bf16 Q/K/V (hi + lo). 6 x 6.3MB.
__device__ __align__(16) __nv_bfloat16 g_Qh[BATCH * SEQ * DIMN];
__device__ __align__(16) __nv_bfloat16 g_Ql[BATCH * SEQ * DIMN];
__device__ __align__(16) __nv_bfloat16 g_Kh[BATCH * SEQ * DIMN];
__device__ __align__(16) __nv_bfloat16 g_Kl[BATCH * SEQ * DIMN];
__device__ __align__(16) __nv_bfloat16 g_Vh[BATCH * SEQ * DIMN];
__device__ __align__(16) __nv_bfloat16 g_Vl[BATCH * SEQ * DIMN];

// ---------------------------------------------------------------------------
__device__ __forceinline__ float fast_exp(float s) {
    float t = s * 1.4426950408889634f;
    t = fminf(fmaxf(t, -120.0f), 120.0f);
    float r = rintf(t);
    float g = (t - r) * 0.69314718055994531f;
    float p = 1.3888889e-3f;
    p = fmaf(p, g, 8.3333333e-3f);
    p = fmaf(p, g, 4.1666667e-2f);
    p = fmaf(p, g, 1.6666667e-1f);
    p = fmaf(p, g, 0.5f);
    p = fmaf(p, g, 1.0f);
    p = fmaf(p, g, 1.0f);
    return p * __int_as_float(((int)r + 127) << 23);
}

__device__ __forceinline__ uint32_t smem_u32(const void* p) {
    return (uint32_t)__cvta_generic_to_shared(p);
}

__device__ __forceinline__ void ldm_x4(uint32_t r[4], uint32_t addr) {
    asm volatile("ldmatrix.sync.aligned.m8n8.x4.shared.b16 {%0,%1,%2,%3}, [%4];"
                 : "=r"(r[0]), "=r"(r[1]), "=r"(r[2]), "=r"(r[3]) : "r"(addr));
}
__device__ __forceinline__ void ldm_x4_t(uint32_t r[4], uint32_t addr) {
    asm volatile("ldmatrix.sync.aligned.m8n8.x4.trans.shared.b16 {%0,%1,%2,%3}, [%4];"
                 : "=r"(r[0]), "=r"(r[1]), "=r"(r[2]), "=r"(r[3]) : "r"(addr));
}
__device__ __forceinline__ void mma_bf16(float c[4], const uint32_t a[4],
                                         uint32_t b0, uint32_t b1) {
    asm volatile(
        "mma.sync.aligned.m16n8k16.row.col.f32.bf16.bf16.f32 "
        "{%0,%1,%2,%3}, {%4,%5,%6,%7}, {%8,%9}, {%0,%1,%2,%3};"
        : "+f"(c[0]), "+f"(c[1]), "+f"(c[2]), "+f"(c[3])
        : "r"(a[0]), "r"(a[1]), "r"(a[2]), "r"(a[3]), "r"(b0), "r"(b1));
}

// ---------------------------------------------------------------------------
// Kernel 1: QKV projection, fp32 SGEMM, epilogue emits split bf16 (hi, lo).
// ---------------------------------------------------------------------------
__global__ __launch_bounds__(256) void qkv_gemm(
    const float* __restrict__ X,
    const float* __restrict__ Wq,
    const float* __restrict__ Wk,
    const float* __restrict__ Wv)
{
    __shared__ float As[16][132];
    __shared__ float Bs[16][132];

    const float* W;
    __nv_bfloat16 *Yh, *Yl;
    if (blockIdx.z == 0)      { W = Wq; Yh = g_Qh; Yl = g_Ql; }
    else if (blockIdx.z == 1) { W = Wk; Yh = g_Kh; Yl = g_Kl; }
    else                      { W = Wv; Yh = g_Vh; Yl = g_Vl; }

    const int tid = threadIdx.x;
    const int tx  = tid & 15;
    const int ty  = tid >> 4;
    const int bm  = blockIdx.x * 128;
    const int bn  = blockIdx.y * 128;

    float acc[8][8];
#pragma unroll
    for (int i = 0; i < 8; i++)
#pragma unroll
        for (int j = 0; j < 8; j++) acc[i][j] = 0.0f;

    for (int k0 = 0; k0 < DIMN; k0 += 16) {
#pragma unroll
        for (int i = 0; i < 2; i++) {
            int s   = tid + 256 * i;
            int row = s >> 2;
            int c4  = (s & 3) << 2;
            float4 va = *(const float4*)(X + (size_t)(bm + row) * DIMN + k0 + c4);
            As[c4 + 0][row] = va.x; As[c4 + 1][row] = va.y;
            As[c4 + 2][row] = va.z; As[c4 + 3][row] = va.w;
            float4 vb = *(const float4*)(W + (size_t)(bn + row) * DIMN + k0 + c4);
            Bs[c4 + 0][row] = vb.x; Bs[c4 + 1][row] = vb.y;
            Bs[c4 + 2][row] = vb.z; Bs[c4 + 3][row] = vb.w;
        }
        __syncthreads();

#pragma unroll
        for (int kk = 0; kk < 16; kk++) {
            float a[8], bf[8];
            float4 a0 = *(const float4*)&As[kk][ty * 8];
            float4 a1 = *(const float4*)&As[kk][ty * 8 + 4];
            a[0] = a0.x; a[1] = a0.y; a[2] = a0.z; a[3] = a0.w;
            a[4] = a1.x; a[5] = a1.y; a[6] = a1.z; a[7] = a1.w;
#pragma unroll
            for (int j = 0; j < 8; j++) bf[j] = Bs[kk][tx + 16 * j];
#pragma unroll
            for (int i = 0; i < 8; i++)
#pragma unroll
                for (int j = 0; j < 8; j++)
                    acc[i][j] = fmaf(a[i], bf[j], acc[i][j]);
        }
        __syncthreads();
    }

#pragma unroll
    for (int i = 0; i < 8; i++) {
        size_t row = (size_t)(bm + ty * 8 + i);
#pragma unroll
        for (int j = 0; j < 8; j++) {
            size_t idx = row * DIMN + bn + tx + 16 * j;
            float v = acc[i][j];
            __nv_bfloat16 h = __float2bfloat16(v);
            Yh[idx] = h;
            Yl[idx] = __float2bfloat16(v - __bfloat162float(h));
        }
    }
}

// ---------------------------------------------------------------------------
// Kernel 2: fused attention on tensor cores (split-bf16 3-pass mma).
// 768 threads = 24 warps: warp w -> head w>>1, q-half w&1 (16 q rows each).
// ---------------------------------------------------------------------------
#define OFF_KH 0
#define OFF_KL 49664
#define OFF_P  99328
#define OFF_PH 150016
#define OFF_PL 180736
#define SMEM_TOTAL 211456

__global__ __launch_bounds__(768, 1) void attn_kernel(float* __restrict__ Out)
{
    extern __shared__ char sm[];
    __nv_bfloat16* sKh = (__nv_bfloat16*)(sm + OFF_KH);   // [TK][KSTR]  (reused for Vh)
    __nv_bfloat16* sKl = (__nv_bfloat16*)(sm + OFF_KL);   // [TK][KSTR]  (reused for Vl)
    float*         sP  = (float*)        (sm + OFF_P);    // [NH][TQ][PST]
    __nv_bfloat16* sPh = (__nv_bfloat16*)(sm + OFF_PH);   // [NH][TQ][PBST]
    __nv_bfloat16* sPl = (__nv_bfloat16*)(sm + OFF_PL);

    const int tid  = threadIdx.x;
    const int wid  = tid >> 5;
    const int lane = tid & 31;
    const int head = wid >> 1;
    const int qh   = wid & 1;
    const int g    = lane >> 2;          // fragment group id
    const int tg   = lane & 3;           // thread-in-group
    const int lr   = lane & 7;

    const int b  = blockIdx.y;
    const int q0 = blockIdx.x * TQ;

    const float SCALE = 0.03608439182435161f;   // 1/sqrt(768)

    // --- Q fragments (registers, once per block): A-frag per 16-d chunk ---
    uint32_t qfh[4][4], qfl[4][4];
    {
        const int qrow = (b * SEQ + q0 + qh * 16 + g) * DIMN + head * HD;
#pragma unroll
        for (int c = 0; c < 4; c++) {
            int c0 = 2 * tg + 16 * c;
            qfh[c][0] = *(const uint32_t*)(g_Qh + qrow + c0);
            qfh[c][1] = *(const uint32_t*)(g_Qh + qrow + 8 * DIMN + c0);
            qfh[c][2] = *(const uint32_t*)(g_Qh + qrow + c0 + 8);
            qfh[c][3] = *(const uint32_t*)(g_Qh + qrow + 8 * DIMN + c0 + 8);
            qfl[c][0] = *(const uint32_t*)(g_Ql + qrow + c0);
            qfl[c][1] = *(const uint32_t*)(g_Ql + qrow + 8 * DIMN + c0);
            qfl[c][2] = *(const uint32_t*)(g_Ql + qrow + c0 + 8);
            qfl[c][3] = *(const uint32_t*)(g_Ql + qrow + 8 * DIMN + c0 + 8);
        }
    }

    float o[8][4];
#pragma unroll
    for (int j = 0; j < 8; j++)
#pragma unroll
        for (int r = 0; r < 4; r++) o[j][r] = 0.0f;

    // ldmatrix per-lane address components
    // K (non-trans B-frags): lanes 0-7: kk+lr,d+0 | 8-15: kk+lr,d+8 | 16-23: kk+8+lr,d+0 | 24-31: kk+8+lr,d+8
    const int kko_k = lr + ((lane >> 4) << 3);
    const int dof_k = ((lane >> 3) & 1) << 3;
    // V (trans B-frags): lanes 0-7: kk+lr,d+0 | 8-15: kk+8+lr,d+0 | 16-23: kk+lr,d+8 | 24-31: kk+8+lr,d+8
    const int kko_v = lr + (((lane >> 3) & 1) << 3);
    const int dof_v = (lane >> 4) << 3;
    // P (A-frags): lanes 0-15: row lane&15, col 0 | 16-31: row lane&15, col 8
    const int prow  = lane & 15;
    const int pcol  = (lane >> 4) << 3;

    const size_t kvbase = (size_t)b * SEQ * DIMN;

#pragma unroll 1
    for (int kt = 0; kt < SEQ; kt += TK) {
        __syncthreads();   // prev AV done: KV / P / Pb reusable

        // --- load K tile (hi+lo) ---
        {
            const size_t gb = kvbase + (size_t)kt * DIMN;
#pragma unroll
            for (int i = 0; i < 4; i++) {
                int s  = tid + 768 * i;
                int r  = s / 96;
                int cc = (s % 96) * 8;
                *(uint4*)(sKh + r * KSTR + cc) = *(const uint4*)(g_Kh + gb + (size_t)r * DIMN + cc);
                *(uint4*)(sKl + r * KSTR + cc) = *(const uint4*)(g_Kl + gb + (size_t)r * DIMN + cc);
            }
        }
        __syncthreads();

        // --- scores: S (16q x 32k) = Qh Kh + Ql Kh + Qh Kl ---
        float s4[4][4];
#pragma unroll
        for (int j = 0; j < 4; j++)
#pragma unroll
            for (int r = 0; r < 4; r++) s4[j][r] = 0.0f;

#pragma unroll
        for (int p = 0; p < 2; p++) {          // n-octet pair (16 kk)
#pragma unroll
            for (int c = 0; c < 4; c++) {      // k16 chunk over d
                int e = (16 * p + kko_k) * KSTR + head * HD + 16 * c + dof_k;
                uint32_t kh[4], kl[4];
                ldm_x4(kh, smem_u32(sKh + e));
                ldm_x4(kl, smem_u32(sKl + e));
                mma_bf16(s4[2 * p],     qfh[c], kh[0], kh[1]);
                mma_bf16(s4[2 * p],     qfl[c], kh[0], kh[1]);
                mma_bf16(s4[2 * p],     qfh[c], kl[0], kl[1]);
                mma_bf16(s4[2 * p + 1], qfh[c], kh[2], kh[3]);
                mma_bf16(s4[2 * p + 1], qfl[c], kh[2], kh[3]);
                mma_bf16(s4[2 * p + 1], qfh[c], kl[2], kl[3]);
            }
        }

        // --- exp and stage to fp32 P smem ---
        {
            float* Pq = sP + (head * TQ + qh * 16) * PST;
#pragma unroll
            for (int j = 0; j < 4; j++) {
                int kk = 8 * j + 2 * tg;
                Pq[g * PST + kk]           = fast_exp(s4[j][0]);
                Pq[g * PST + kk + 1]       = fast_exp(s4[j][1]);
                Pq[(g + 8) * PST + kk]     = fast_exp(s4[j][2]);
                Pq[(g + 8) * PST + kk + 1] = fast_exp(s4[j][3]);
            }
        }
        __syncthreads();   // K smem free, P complete

        // --- normalize across heads -> bf16 hi/lo P ---
#pragma unroll
        for (int base = 0; base < 1024; base += 768) {
            int idx = tid + base;
            if (idx < 1024) {
                int q  = idx >> 5;
                int kk = idx & 31;
                float e[NH];
                float den = 0.0f;
#pragma unroll
                for (int h = 0; h < NH; h++) {
                    e[h] = sP[(h * TQ + q) * PST + kk];
                    den += e[h];
                }
                float sc = __fdividef(SCALE, den);
#pragma unroll
                for (int h = 0; h < NH; h++) {
                    float pv = e[h] * sc;
                    __nv_bfloat16 hh = __float2bfloat16(pv);
                    sPh[(h * TQ + q) * PBST + kk] = hh;
                    sPl[(h * TQ + q) * PBST + kk] =
                        __float2bfloat16(pv - __bfloat162float(hh));
                }
            }
        }

        // --- load V tile into K buffers (K is dead) ---
        {
            const size_t gb = kvbase + (size_t)kt * DIMN;
#pragma unroll
            for (int i = 0; i < 4; i++) {
                int s  = tid + 768 * i;
                int r  = s / 96;
                int cc = (s % 96) * 8;
                *(uint4*)(sKh + r * KSTR + cc) = *(const uint4*)(g_Vh + gb + (size_t)r * DIMN + cc);
                *(uint4*)(sKl + r * KSTR + cc) = *(const uint4*)(g_Vl + gb + (size_t)r * DIMN + cc);
            }
        }
        __syncthreads();   // V + Pb ready

        // --- AV: O (16q x 64d) += Ph Vh + Pl Vh + Ph Vl ---
#pragma unroll
        for (int c = 0; c < 2; c++) {          // k16 chunk over kk
            int pe = (head * TQ + qh * 16 + prow) * PBST + 16 * c + pcol;
            uint32_t ph[4], pl[4];
            ldm_x4(ph, smem_u32(sPh + pe));
            ldm_x4(pl, smem_u32(sPl + pe));
#pragma unroll
            for (int dp = 0; dp < 4; dp++) {   // d-octet pair (16 d)
                int e = (16 * c + kko_v) * KSTR + head * HD + 16 * dp + dof_v;
                uint32_t vh[4], vl[4];
                ldm_x4_t(vh, smem_u32(sKh + e));
                ldm_x4_t(vl, smem_u32(sKl + e));
                mma_bf16(o[2 * dp],     ph, vh[0], vh[1]);
                mma_bf16(o[2 * dp],     pl, vh[0], vh[1]);
                mma_bf16(o[2 * dp],     ph, vl[0], vl[1]);
                mma_bf16(o[2 * dp + 1], ph, vh[2], vh[3]);
                mma_bf16(o[2 * dp + 1], pl, vh[2], vh[3]);
                mma_bf16(o[2 * dp + 1], ph, vl[2], vl[3]);
            }
        }
    }

    // --- writeout ---
    float* Ob = Out + (size_t)(b * SEQ + q0 + qh * 16) * DIMN + head * HD;
#pragma unroll
    for (int j = 0; j < 8; j++) {
        int d = 8 * j + 2 * tg;
        *(float2*)(Ob + (size_t)g * DIMN + d)       = make_float2(o[j][0], o[j][1]);
        *(float2*)(Ob + (size_t)(g + 8) * DIMN + d) = make_float2(o[j][2], o[j][3]);
    }
}

// ---------------------------------------------------------------------------
extern "C" void kernel_launch(void* const* d_in, const int* in_sizes, int n_in,
                              void* d_out, int out_size)
{
    const float* x  = (const float*)d_in[0];
    const float* Wq = (const float*)d_in[1];
    const float* Wk = (const float*)d_in[2];
    const float* Wv = (const float*)d_in[3];
    float* out = (float*)d_out;

    dim3 g1(4096 / 128, DIMN / 128, 3);
    qkv_gemm<<<g1, 256>>>(x, Wq, Wk, Wv);

    cudaFuncSetAttribute(attn_kernel, cudaFuncAttributeMaxDynamicSharedMemorySize, SMEM_TOTAL);
    dim3 g2(SEQ / TQ, BATCH);
    attn_kernel<<<g2, 768, SMEM_TOTAL>>>(out);
}

// round 5
// speedup vs baseline: 1.5493x; 1.1070x over previous
#include <cuda_runtime.h>
#include <cuda_bf16.h>
#include <cstdint>

#define BATCH 2
#define SEQ   2048
#define DIMN  768
#define NH    12
#define HD    64

#define TQ 32
#define TK 32

#define KSTR 776           /* bf16 row stride: 1552B = 97*16 -> 16B aligned, conflict-free ldmatrix */
#define PST  18            /* fp32 exp-exchange row stride (floats); even -> float2-aligned */

// smem layout (bytes)
#define OFF_A   0                         /* K tile: hi, then lo            */
#define A_LO    49664                     /* 32*776*2                        */
#define OFF_B   99328                     /* V tile: hi, then lo             */
#define B_LO    49664
#define OFF_P   198656                    /* sP fp32 [NH][32][PST] = 27648   */
#define OFF_I   226304                    /* sInv fp32 [2][32][PST] = 4608   */
#define SMEM_TOTAL 230912

// split-bf16 Q/K/V (hi + lo)
__device__ __align__(16) __nv_bfloat16 g_Qh[BATCH * SEQ * DIMN];
__device__ __align__(16) __nv_bfloat16 g_Ql[BATCH * SEQ * DIMN];
__device__ __align__(16) __nv_bfloat16 g_Kh[BATCH * SEQ * DIMN];
__device__ __align__(16) __nv_bfloat16 g_Kl[BATCH * SEQ * DIMN];
__device__ __align__(16) __nv_bfloat16 g_Vh[BATCH * SEQ * DIMN];
__device__ __align__(16) __nv_bfloat16 g_Vl[BATCH * SEQ * DIMN];

// ---------------------------------------------------------------------------
__device__ __forceinline__ float fast_exp(float s) {
    float t = s * 1.4426950408889634f;
    t = fminf(fmaxf(t, -120.0f), 120.0f);
    float r = rintf(t);
    float g = (t - r) * 0.69314718055994531f;
    float p = 1.3888889e-3f;
    p = fmaf(p, g, 8.3333333e-3f);
    p = fmaf(p, g, 4.1666667e-2f);
    p = fmaf(p, g, 1.6666667e-1f);
    p = fmaf(p, g, 0.5f);
    p = fmaf(p, g, 1.0f);
    p = fmaf(p, g, 1.0f);
    return p * __int_as_float(((int)r + 127) << 23);
}

__device__ __forceinline__ uint32_t smem_u32(const void* p) {
    return (uint32_t)__cvta_generic_to_shared(p);
}
__device__ __forceinline__ void ldm_x4(uint32_t r[4], uint32_t addr) {
    asm volatile("ldmatrix.sync.aligned.m8n8.x4.shared.b16 {%0,%1,%2,%3}, [%4];"
                 : "=r"(r[0]), "=r"(r[1]), "=r"(r[2]), "=r"(r[3]) : "r"(addr));
}
__device__ __forceinline__ void ldm_x4_t(uint32_t r[4], uint32_t addr) {
    asm volatile("ldmatrix.sync.aligned.m8n8.x4.trans.shared.b16 {%0,%1,%2,%3}, [%4];"
                 : "=r"(r[0]), "=r"(r[1]), "=r"(r[2]), "=r"(r[3]) : "r"(addr));
}
__device__ __forceinline__ void mma_bf16(float c[4], const uint32_t a[4],
                                         uint32_t b0, uint32_t b1) {
    asm volatile(
        "mma.sync.aligned.m16n8k16.row.col.f32.bf16.bf16.f32 "
        "{%0,%1,%2,%3}, {%4,%5,%6,%7}, {%8,%9}, {%0,%1,%2,%3};"
        : "+f"(c[0]), "+f"(c[1]), "+f"(c[2]), "+f"(c[3])
        : "r"(a[0]), "r"(a[1]), "r"(a[2]), "r"(a[3]), "r"(b0), "r"(b1));
}
__device__ __forceinline__ void cp16(uint32_t saddr, const void* gaddr) {
    asm volatile("cp.async.cg.shared.global [%0], [%1], 16;"
                 :: "r"(saddr), "l"(gaddr));
}
__device__ __forceinline__ void cp_commit() {
    asm volatile("cp.async.commit_group;" ::: "memory");
}
template <int N>
__device__ __forceinline__ void cp_wait() {
    asm volatile("cp.async.wait_group %0;" :: "n"(N) : "memory");
}
__device__ __forceinline__ uint32_t packbf(float a, float b) {
    __nv_bfloat162 h = __floats2bfloat162_rn(a, b);   // .x=a -> low half (col 2tg)
    return *(uint32_t*)&h;
}

// ---------------------------------------------------------------------------
// Kernel 1: QKV projection, fp32 SGEMM, epilogue emits split bf16 (hi, lo).
// ---------------------------------------------------------------------------
__global__ __launch_bounds__(256) void qkv_gemm(
    const float* __restrict__ X,
    const float* __restrict__ Wq,
    const float* __restrict__ Wk,
    const float* __restrict__ Wv)
{
    __shared__ float As[16][132];
    __shared__ float Bs[16][132];

    const float* W;
    __nv_bfloat16 *Yh, *Yl;
    if (blockIdx.z == 0)      { W = Wq; Yh = g_Qh; Yl = g_Ql; }
    else if (blockIdx.z == 1) { W = Wk; Yh = g_Kh; Yl = g_Kl; }
    else                      { W = Wv; Yh = g_Vh; Yl = g_Vl; }

    const int tid = threadIdx.x;
    const int tx  = tid & 15;
    const int ty  = tid >> 4;
    const int bm  = blockIdx.x * 128;
    const int bn  = blockIdx.y * 128;

    float acc[8][8];
#pragma unroll
    for (int i = 0; i < 8; i++)
#pragma unroll
        for (int j = 0; j < 8; j++) acc[i][j] = 0.0f;

    for (int k0 = 0; k0 < DIMN; k0 += 16) {
#pragma unroll
        for (int i = 0; i < 2; i++) {
            int s   = tid + 256 * i;
            int row = s >> 2;
            int c4  = (s & 3) << 2;
            float4 va = *(const float4*)(X + (size_t)(bm + row) * DIMN + k0 + c4);
            As[c4 + 0][row] = va.x; As[c4 + 1][row] = va.y;
            As[c4 + 2][row] = va.z; As[c4 + 3][row] = va.w;
            float4 vb = *(const float4*)(W + (size_t)(bn + row) * DIMN + k0 + c4);
            Bs[c4 + 0][row] = vb.x; Bs[c4 + 1][row] = vb.y;
            Bs[c4 + 2][row] = vb.z; Bs[c4 + 3][row] = vb.w;
        }
        __syncthreads();

#pragma unroll
        for (int kk = 0; kk < 16; kk++) {
            float a[8], bf[8];
            float4 a0 = *(const float4*)&As[kk][ty * 8];
            float4 a1 = *(const float4*)&As[kk][ty * 8 + 4];
            a[0] = a0.x; a[1] = a0.y; a[2] = a0.z; a[3] = a0.w;
            a[4] = a1.x; a[5] = a1.y; a[6] = a1.z; a[7] = a1.w;
#pragma unroll
            for (int j = 0; j < 8; j++) bf[j] = Bs[kk][tx + 16 * j];
#pragma unroll
            for (int i = 0; i < 8; i++)
#pragma unroll
                for (int j = 0; j < 8; j++)
                    acc[i][j] = fmaf(a[i], bf[j], acc[i][j]);
        }
        __syncthreads();
    }

#pragma unroll
    for (int i = 0; i < 8; i++) {
        size_t row = (size_t)(bm + ty * 8 + i);
#pragma unroll
        for (int j = 0; j < 8; j++) {
            size_t idx = row * DIMN + bn + tx + 16 * j;
            float v = acc[i][j];
            __nv_bfloat16 h = __float2bfloat16(v);
            Yh[idx] = h;
            Yl[idx] = __float2bfloat16(v - __bfloat162float(h));
        }
    }
}

// ---------------------------------------------------------------------------
// Kernel 2: fused attention. 768 thr = 24 warps; warp = (head, q-half of 16).
// Register-resident P (scores-out frag == AV A-frag layout), cp.async
// prefetch of K/V with disjoint buffer lifetimes, k-split den exchange.
// ---------------------------------------------------------------------------
__global__ __launch_bounds__(768, 1) void attn_kernel(float* __restrict__ Out)
{
    extern __shared__ char sm[];
    __nv_bfloat16* sKh = (__nv_bfloat16*)(sm + OFF_A);
    __nv_bfloat16* sKl = (__nv_bfloat16*)(sm + OFF_A + A_LO);
    __nv_bfloat16* sVh = (__nv_bfloat16*)(sm + OFF_B);
    __nv_bfloat16* sVl = (__nv_bfloat16*)(sm + OFF_B + B_LO);
    float*         sP  = (float*)(sm + OFF_P);    // [NH][32][PST]
    float*         sI  = (float*)(sm + OFF_I);    // [2][32][PST]

    const int tid  = threadIdx.x;
    const int wid  = tid >> 5;
    const int lane = tid & 31;
    const int head = wid >> 1;
    const int qh   = wid & 1;
    const int g    = lane >> 2;
    const int tg   = lane & 3;
    const int lr   = lane & 7;

    const int b  = blockIdx.y;
    const int q0 = blockIdx.x * TQ;

    const float SCALE = 0.03608439182435161f;   // 1/sqrt(768)

    // --- Q A-fragments in registers (per warp: 16q x 64d, hi+lo) ---
    uint32_t qfh[4][4], qfl[4][4];
    {
        const int qrow = (b * SEQ + q0 + qh * 16 + g) * DIMN + head * HD;
#pragma unroll
        for (int c = 0; c < 4; c++) {
            int c0 = 2 * tg + 16 * c;
            qfh[c][0] = *(const uint32_t*)(g_Qh + qrow + c0);
            qfh[c][1] = *(const uint32_t*)(g_Qh + qrow + 8 * DIMN + c0);
            qfh[c][2] = *(const uint32_t*)(g_Qh + qrow + c0 + 8);
            qfh[c][3] = *(const uint32_t*)(g_Qh + qrow + 8 * DIMN + c0 + 8);
            qfl[c][0] = *(const uint32_t*)(g_Ql + qrow + c0);
            qfl[c][1] = *(const uint32_t*)(g_Ql + qrow + 8 * DIMN + c0);
            qfl[c][2] = *(const uint32_t*)(g_Ql + qrow + c0 + 8);
            qfl[c][3] = *(const uint32_t*)(g_Ql + qrow + 8 * DIMN + c0 + 8);
        }
    }

    float o[8][4];
#pragma unroll
    for (int j = 0; j < 8; j++)
#pragma unroll
        for (int r = 0; r < 4; r++) o[j][r] = 0.0f;

    // ldmatrix lane address components (as validated in prior rounds)
    const int kko_k = lr + ((lane >> 4) << 3);
    const int dof_k = ((lane >> 3) & 1) << 3;
    const int kko_v = lr + (((lane >> 3) & 1) << 3);
    const int dof_v = (lane >> 4) << 3;

    const size_t kvbase = (size_t)b * SEQ * DIMN;

    // cp.async tile loader: 8 x 16B per thread (4 hi + 4 lo)
    auto load_tile = [&](__nv_bfloat16* dh, __nv_bfloat16* dl,
                         const __nv_bfloat16* gh, const __nv_bfloat16* gl,
                         int kt) {
        const size_t gb = kvbase + (size_t)kt * DIMN;
#pragma unroll
        for (int i = 0; i < 4; i++) {
            int s  = tid + 768 * i;
            int r  = s / 96;
            int cc = (s % 96) * 8;
            cp16(smem_u32(dh + r * KSTR + cc), gh + gb + (size_t)r * DIMN + cc);
            cp16(smem_u32(dl + r * KSTR + cc), gl + gb + (size_t)r * DIMN + cc);
        }
    };

    // prologue: K(0) then V(0) in flight
    load_tile(sKh, sKl, g_Kh, g_Kl, 0); cp_commit();
    load_tile(sVh, sVl, g_Vh, g_Vl, 0); cp_commit();
    cp_wait<1>();        // K(0) landed
    __syncthreads();

    float* Pq = sP + (head * 32 + qh * 16) * PST;
    float s4[4][4];

#pragma unroll 1
    for (int kt = 0; kt < SEQ; kt += TK) {
        const bool has_next = (kt + TK) < SEQ;

        // ---- scores from K buffer (hi: 3-pass split bf16) ----
#pragma unroll
        for (int j = 0; j < 4; j++)
#pragma unroll
            for (int r = 0; r < 4; r++) s4[j][r] = 0.0f;

#pragma unroll
        for (int p = 0; p < 2; p++) {
#pragma unroll
            for (int c = 0; c < 4; c++) {
                int e = (16 * p + kko_k) * KSTR + head * HD + 16 * c + dof_k;
                uint32_t kh[4], kl[4];
                ldm_x4(kh, smem_u32(sKh + e));
                ldm_x4(kl, smem_u32(sKl + e));
                mma_bf16(s4[2 * p],     qfh[c], kh[0], kh[1]);
                mma_bf16(s4[2 * p],     qfl[c], kh[0], kh[1]);
                mma_bf16(s4[2 * p],     qfh[c], kl[0], kl[1]);
                mma_bf16(s4[2 * p + 1], qfh[c], kh[2], kh[3]);
                mma_bf16(s4[2 * p + 1], qfl[c], kh[2], kh[3]);
                mma_bf16(s4[2 * p + 1], qfh[c], kl[2], kl[3]);
            }
        }

        // ---- exp in regs (overwrite s4) ----
#pragma unroll
        for (int j = 0; j < 4; j++)
#pragma unroll
            for (int r = 0; r < 4; r++) s4[j][r] = fast_exp(s4[j][r]);

        // ---- half 0 (kk 0..15, j=0,1): exchange + den ----
#pragma unroll
        for (int j = 0; j < 2; j++) {
            *(float2*)(Pq + g * PST + 8 * j + 2 * tg)       = make_float2(s4[j][0], s4[j][1]);
            *(float2*)(Pq + (g + 8) * PST + 8 * j + 2 * tg) = make_float2(s4[j][2], s4[j][3]);
        }
        __syncthreads();                       // S2: scores done -> K buffer free
        if (has_next) load_tile(sKh, sKl, g_Kh, g_Kl, kt + TK);
        cp_commit();

        if (tid < 512) {
            int q = tid >> 4, k = tid & 15;
            float den = 0.0f;
#pragma unroll
            for (int h = 0; h < NH; h++) den += sP[(h * 32 + q) * PST + k];
            sI[q * PST + k] = __fdividef(SCALE, den);
        }
        __syncthreads();                       // S3

        // ---- half 1 (kk 16..31, j=2,3) ----
#pragma unroll
        for (int j = 2; j < 4; j++) {
            *(float2*)(Pq + g * PST + 8 * (j - 2) + 2 * tg)       = make_float2(s4[j][0], s4[j][1]);
            *(float2*)(Pq + (g + 8) * PST + 8 * (j - 2) + 2 * tg) = make_float2(s4[j][2], s4[j][3]);
        }
        __syncthreads();                       // S4

        if (tid < 512) {
            int q = tid >> 4, k = tid & 15;
            float den = 0.0f;
#pragma unroll
            for (int h = 0; h < NH; h++) den += sP[(h * 32 + q) * PST + k];
            sI[32 * PST + q * PST + k] = __fdividef(SCALE, den);
        }
        if (has_next) cp_wait<1>(); else cp_wait<0>();   // V(t) landed
        __syncthreads();                       // S5

        // ---- build P A-frags in registers (hi + lo) ----
        uint32_t ph[2][4], pl[2][4];
        {
            const int qr = qh * 16 + g;
#pragma unroll
            for (int c = 0; c < 2; c++) {
                const float* invh = sI + c * (32 * PST);
#pragma unroll
                for (int hf = 0; hf < 2; hf++) {   // row g (hf=0) / g+8 (hf=1)
                    const float* ir = invh + (qr + 8 * hf) * PST + 2 * tg;
                    float2 iv0 = *(const float2*)(ir);
                    float2 iv1 = *(const float2*)(ir + 8);
                    float p0 = s4[2 * c][2 * hf]     * iv0.x;
                    float p1 = s4[2 * c][2 * hf + 1] * iv0.y;
                    float p2 = s4[2 * c + 1][2 * hf]     * iv1.x;
                    float p3 = s4[2 * c + 1][2 * hf + 1] * iv1.y;
                    uint32_t h0 = packbf(p0, p1);
                    uint32_t h1 = packbf(p2, p3);
                    __nv_bfloat162 b0 = *(__nv_bfloat162*)&h0;
                    __nv_bfloat162 b1 = *(__nv_bfloat162*)&h1;
                    ph[c][hf]     = h0;
                    ph[c][2 + hf] = h1;
                    pl[c][hf]     = packbf(p0 - __bfloat162float(b0.x),
                                           p1 - __bfloat162float(b0.y));
                    pl[c][2 + hf] = packbf(p2 - __bfloat162float(b1.x),
                                           p3 - __bfloat162float(b1.y));
                }
            }
        }

        // ---- AV from V buffer ----
#pragma unroll
        for (int c = 0; c < 2; c++) {
#pragma unroll
            for (int dp = 0; dp < 4; dp++) {
                int e = (16 * c + kko_v) * KSTR + head * HD + 16 * dp + dof_v;
                uint32_t vh[4], vl[4];
                ldm_x4_t(vh, smem_u32(sVh + e));
                ldm_x4_t(vl, smem_u32(sVl + e));
                mma_bf16(o[2 * dp],     ph[c], vh[0], vh[1]);
                mma_bf16(o[2 * dp],     pl[c], vh[0], vh[1]);
                mma_bf16(o[2 * dp],     ph[c], vl[0], vl[1]);
                mma_bf16(o[2 * dp + 1], ph[c], vh[2], vh[3]);
                mma_bf16(o[2 * dp + 1], pl[c], vh[2], vh[3]);
                mma_bf16(o[2 * dp + 1], ph[c], vl[2], vl[3]);
            }
        }

        cp_wait<0>();                          // K(t+1) landed
        __syncthreads();                       // S6: AV done -> V buffer free
        if (has_next) load_tile(sVh, sVl, g_Vh, g_Vl, kt + TK);
        cp_commit();
    }

    // ---- writeout ----
    float* Ob = Out + (size_t)(b * SEQ + q0 + qh * 16) * DIMN + head * HD;
#pragma unroll
    for (int j = 0; j < 8; j++) {
        int d = 8 * j + 2 * tg;
        *(float2*)(Ob + (size_t)g * DIMN + d)       = make_float2(o[j][0], o[j][1]);
        *(float2*)(Ob + (size_t)(g + 8) * DIMN + d) = make_float2(o[j][2], o[j][3]);
    }
}

// ---------------------------------------------------------------------------
extern "C" void kernel_launch(void* const* d_in, const int* in_sizes, int n_in,
                              void* d_out, int out_size)
{
    const float* x  = (const float*)d_in[0];
    const float* Wq = (const float*)d_in[1];
    const float* Wk = (const float*)d_in[2];
    const float* Wv = (const float*)d_in[3];
    float* out = (float*)d_out;

    dim3 g1(4096 / 128, DIMN / 128, 3);
    qkv_gemm<<<g1, 256>>>(x, Wq, Wk, Wv);

    cudaFuncSetAttribute(attn_kernel, cudaFuncAttributeMaxDynamicSharedMemorySize, SMEM_TOTAL);
    dim3 g2(SEQ / TQ, BATCH);
    attn_kernel<<<g2, 768, SMEM_TOTAL>>>(out);
}

// round 7
// speedup vs baseline: 1.9086x; 1.2319x over previous
#include <cuda_runtime.h>
#include <cuda_bf16.h>
#include <cstdint>

#define BATCH 2
#define SEQ   2048
#define DIMN  768
#define NH    12
#define HD    64

#define TQ 32
#define TK 32

#define KSTR 776           /* bf16 row stride: 1552B = 97*16 -> 16B aligned, conflict-free ldmatrix */
#define PST  18            /* fp32 exp-exchange row stride (floats); even -> float2-aligned */

// attn smem layout (bytes)
#define OFF_A   0                         /* K tile: hi, then lo            */
#define A_LO    49664                     /* 32*776*2                        */
#define OFF_B   99328                     /* V tile: hi, then lo             */
#define B_LO    49664
#define OFF_P   198656                    /* sP fp32 [NH][32][PST] = 27648   */
#define OFF_I   226304                    /* sInv fp32 [2][32][PST] = 4608   */
#define SMEM_TOTAL 230912

// split-bf16 operands
__device__ __align__(16) __nv_bfloat16 g_Xh[4096 * DIMN];
__device__ __align__(16) __nv_bfloat16 g_Xl[4096 * DIMN];
__device__ __align__(16) __nv_bfloat16 g_Wh[3 * DIMN * DIMN];
__device__ __align__(16) __nv_bfloat16 g_Wl[3 * DIMN * DIMN];

// split-bf16 Q/K/V (hi + lo)
__device__ __align__(16) __nv_bfloat16 g_Qh[BATCH * SEQ * DIMN];
__device__ __align__(16) __nv_bfloat16 g_Ql[BATCH * SEQ * DIMN];
__device__ __align__(16) __nv_bfloat16 g_Kh[BATCH * SEQ * DIMN];
__device__ __align__(16) __nv_bfloat16 g_Kl[BATCH * SEQ * DIMN];
__device__ __align__(16) __nv_bfloat16 g_Vh[BATCH * SEQ * DIMN];
__device__ __align__(16) __nv_bfloat16 g_Vl[BATCH * SEQ * DIMN];

// ---------------------------------------------------------------------------
__device__ __forceinline__ float fast_exp(float s) {
    float t = s * 1.4426950408889634f;
    t = fminf(fmaxf(t, -120.0f), 120.0f);
    float r = rintf(t);
    float g = (t - r) * 0.69314718055994531f;
    float p = 1.3888889e-3f;
    p = fmaf(p, g, 8.3333333e-3f);
    p = fmaf(p, g, 4.1666667e-2f);
    p = fmaf(p, g, 1.6666667e-1f);
    p = fmaf(p, g, 0.5f);
    p = fmaf(p, g, 1.0f);
    p = fmaf(p, g, 1.0f);
    return p * __int_as_float(((int)r + 127) << 23);
}

__device__ __forceinline__ uint32_t smem_u32(const void* p) {
    return (uint32_t)__cvta_generic_to_shared(p);
}
__device__ __forceinline__ void ldm_x4(uint32_t r[4], uint32_t addr) {
    asm volatile("ldmatrix.sync.aligned.m8n8.x4.shared.b16 {%0,%1,%2,%3}, [%4];"
                 : "=r"(r[0]), "=r"(r[1]), "=r"(r[2]), "=r"(r[3]) : "r"(addr));
}
__device__ __forceinline__ void ldm_x4_t(uint32_t r[4], uint32_t addr) {
    asm volatile("ldmatrix.sync.aligned.m8n8.x4.trans.shared.b16 {%0,%1,%2,%3}, [%4];"
                 : "=r"(r[0]), "=r"(r[1]), "=r"(r[2]), "=r"(r[3]) : "r"(addr));
}
__device__ __forceinline__ void mma_bf16(float c[4], const uint32_t a[4],
                                         uint32_t b0, uint32_t b1) {
    asm volatile(
        "mma.sync.aligned.m16n8k16.row.col.f32.bf16.bf16.f32 "
        "{%0,%1,%2,%3}, {%4,%5,%6,%7}, {%8,%9}, {%0,%1,%2,%3};"
        : "+f"(c[0]), "+f"(c[1]), "+f"(c[2]), "+f"(c[3])
        : "r"(a[0]), "r"(a[1]), "r"(a[2]), "r"(a[3]), "r"(b0), "r"(b1));
}
__device__ __forceinline__ void cp16(uint32_t saddr, const void* gaddr) {
    asm volatile("cp.async.cg.shared.global [%0], [%1], 16;"
                 :: "r"(saddr), "l"(gaddr));
}
__device__ __forceinline__ void cp_commit() {
    asm volatile("cp.async.commit_group;" ::: "memory");
}
template <int N>
__device__ __forceinline__ void cp_wait() {
    asm volatile("cp.async.wait_group %0;" :: "n"(N) : "memory");
}
__device__ __forceinline__ uint32_t packbf(float a, float b) {
    __nv_bfloat162 h = __floats2bfloat162_rn(a, b);   // .x=a -> low half
    return *(uint32_t*)&h;
}

// ---------------------------------------------------------------------------
// Kernel 0: fp32 -> split bf16 (hi, lo), vectorized.
// FIX vs R6: destination is selected INSIDE device code (dst_sel/offset) —
// __device__ globals must never be passed as kernel arguments from host.
// ---------------------------------------------------------------------------
__global__ __launch_bounds__(256) void cvt_split(
    const float* __restrict__ src,
    int dst_sel,            /* 0 = X buffers, 1 = W buffers */
    int off_elems,          /* element offset into destination */
    int n4)
{
    int i = blockIdx.x * 256 + threadIdx.x;
    if (i >= n4) return;
    __nv_bfloat16 *dh, *dl;
    if (dst_sel == 0) { dh = g_Xh; dl = g_Xl; }
    else              { dh = g_Wh; dl = g_Wl; }
    dh += off_elems;
    dl += off_elems;

    float4 v = ((const float4*)src)[i];
    __nv_bfloat162 h0 = __floats2bfloat162_rn(v.x, v.y);
    __nv_bfloat162 h1 = __floats2bfloat162_rn(v.z, v.w);
    __nv_bfloat162 l0 = __floats2bfloat162_rn(v.x - __bfloat162float(h0.x),
                                              v.y - __bfloat162float(h0.y));
    __nv_bfloat162 l1 = __floats2bfloat162_rn(v.z - __bfloat162float(h1.x),
                                              v.w - __bfloat162float(h1.y));
    ((__nv_bfloat162*)dh)[2 * i]     = h0;
    ((__nv_bfloat162*)dh)[2 * i + 1] = h1;
    ((__nv_bfloat162*)dl)[2 * i]     = l0;
    ((__nv_bfloat162*)dl)[2 * i + 1] = l1;
}

// ---------------------------------------------------------------------------
// Kernel 1: QKV projection on tensor cores, split-bf16 3-pass.
// Y = X @ W^T. Block tile 128x128, K-step 32, double-buffered cp.async.
// 256 thr = 8 warps (2m x 4n), warp tile 64x32.
// ---------------------------------------------------------------------------
#define Q_AH  0
#define Q_AL  10240
#define Q_BH  20480
#define Q_BL  30720
#define Q_STAGE 40960
#define Q_SMEM  81920

__global__ __launch_bounds__(256, 1) void qkv_mma()
{
    extern __shared__ char qsm[];

    const int tid  = threadIdx.x;
    const int wid  = tid >> 5;
    const int lane = tid & 31;
    const int g    = lane >> 2;
    const int tg   = lane & 3;
    const int lr   = lane & 7;

    const int warpM = (wid & 1) * 64;
    const int warpN = (wid >> 1) * 32;

    const int bm  = blockIdx.x * 128;
    const int bn  = blockIdx.y * 128;
    const int mat = blockIdx.z;

    const __nv_bfloat16* Wh = g_Wh + (size_t)mat * DIMN * DIMN;
    const __nv_bfloat16* Wl = g_Wl + (size_t)mat * DIMN * DIMN;
    __nv_bfloat16 *Yh, *Yl;
    if (mat == 0)      { Yh = g_Qh; Yl = g_Ql; }
    else if (mat == 1) { Yh = g_Kh; Yl = g_Kl; }
    else               { Yh = g_Vh; Yl = g_Vl; }

    // ldmatrix lane addressing (validated patterns)
    const int prow = lane & 15;                 // A frags
    const int pcol = (lane >> 4) << 3;
    const int kko  = lr + ((lane >> 4) << 3);   // B frags (n16 x k16)
    const int dof  = ((lane >> 3) & 1) << 3;

    float acc[4][4][4];
#pragma unroll
    for (int i = 0; i < 4; i++)
#pragma unroll
        for (int j = 0; j < 4; j++)
#pragma unroll
            for (int r = 0; r < 4; r++) acc[i][j][r] = 0.0f;

    auto load_stage = [&](int stage, int k0) {
        uint32_t base = smem_u32(qsm) + stage * Q_STAGE;
#pragma unroll
        for (int i = 0; i < 2; i++) {
            int s  = tid + 256 * i;
            int r  = s >> 2;
            int cc = (s & 3) * 8;
            uint32_t off = (uint32_t)(r * 80 + (s & 3) * 16);
            const size_t ga = (size_t)(bm + r) * DIMN + k0 + cc;
            cp16(base + Q_AH + off, g_Xh + ga);
            cp16(base + Q_AL + off, g_Xl + ga);
            const size_t gb = (size_t)(bn + r) * DIMN + k0 + cc;
            cp16(base + Q_BH + off, Wh + gb);
            cp16(base + Q_BL + off, Wl + gb);
        }
    };

    load_stage(0, 0);  cp_commit();
    load_stage(1, 32); cp_commit();

    const int NSTEP = DIMN / 32;   // 24
#pragma unroll 1
    for (int step = 0; step < NSTEP; step++) {
        cp_wait<1>();
        __syncthreads();

        uint32_t base = smem_u32(qsm) + (step & 1) * Q_STAGE;
#pragma unroll
        for (int c = 0; c < 2; c++) {
            uint32_t ah[4][4], al[4][4];
#pragma unroll
            for (int i = 0; i < 4; i++) {
                uint32_t ao = base + Q_AH +
                    (uint32_t)((warpM + 16 * i + prow) * 80 + c * 32 + pcol * 2);
                ldm_x4(ah[i], ao);
                ldm_x4(al[i], ao + (Q_AL - Q_AH));
            }
            uint32_t bh[2][4], bl[2][4];
#pragma unroll
            for (int p = 0; p < 2; p++) {
                uint32_t bo = base + Q_BH +
                    (uint32_t)((warpN + 16 * p + kko) * 80 + c * 32 + dof * 2);
                ldm_x4(bh[p], bo);
                ldm_x4(bl[p], bo + (Q_BL - Q_BH));
            }
#pragma unroll
            for (int i = 0; i < 4; i++)
#pragma unroll
                for (int p = 0; p < 2; p++) {
                    mma_bf16(acc[i][2 * p],     ah[i], bh[p][0], bh[p][1]);
                    mma_bf16(acc[i][2 * p],     al[i], bh[p][0], bh[p][1]);
                    mma_bf16(acc[i][2 * p],     ah[i], bl[p][0], bl[p][1]);
                    mma_bf16(acc[i][2 * p + 1], ah[i], bh[p][2], bh[p][3]);
                    mma_bf16(acc[i][2 * p + 1], al[i], bh[p][2], bh[p][3]);
                    mma_bf16(acc[i][2 * p + 1], ah[i], bl[p][2], bl[p][3]);
                }
        }
        __syncthreads();
        if (step + 2 < NSTEP) {
            load_stage(step & 1, (step + 2) * 32);
        }
        cp_commit();   // keep group count in lockstep even when empty
    }

    // epilogue: split-bf16 store
#pragma unroll
    for (int i = 0; i < 4; i++) {
        int row0 = bm + warpM + 16 * i + g;
#pragma unroll
        for (int j = 0; j < 4; j++) {
            int col = bn + warpN + 8 * j + 2 * tg;
            float c0 = acc[i][j][0], c1 = acc[i][j][1];
            float c2 = acc[i][j][2], c3 = acc[i][j][3];
            uint32_t h01 = packbf(c0, c1);
            uint32_t h23 = packbf(c2, c3);
            __nv_bfloat162 b01 = *(__nv_bfloat162*)&h01;
            __nv_bfloat162 b23 = *(__nv_bfloat162*)&h23;
            uint32_t l01 = packbf(c0 - __bfloat162float(b01.x),
                                  c1 - __bfloat162float(b01.y));
            uint32_t l23 = packbf(c2 - __bfloat162float(b23.x),
                                  c3 - __bfloat162float(b23.y));
            *(uint32_t*)(Yh + (size_t)row0 * DIMN + col)       = h01;
            *(uint32_t*)(Yh + (size_t)(row0 + 8) * DIMN + col) = h23;
            *(uint32_t*)(Yl + (size_t)row0 * DIMN + col)       = l01;
            *(uint32_t*)(Yl + (size_t)(row0 + 8) * DIMN + col) = l23;
        }
    }
}

// ---------------------------------------------------------------------------
// Kernel 2: fused attention (unchanged from R5 passing version).
// ---------------------------------------------------------------------------
__global__ __launch_bounds__(768, 1) void attn_kernel(float* __restrict__ Out)
{
    extern __shared__ char sm[];
    __nv_bfloat16* sKh = (__nv_bfloat16*)(sm + OFF_A);
    __nv_bfloat16* sKl = (__nv_bfloat16*)(sm + OFF_A + A_LO);
    __nv_bfloat16* sVh = (__nv_bfloat16*)(sm + OFF_B);
    __nv_bfloat16* sVl = (__nv_bfloat16*)(sm + OFF_B + B_LO);
    float*         sP  = (float*)(sm + OFF_P);
    float*         sI  = (float*)(sm + OFF_I);

    const int tid  = threadIdx.x;
    const int wid  = tid >> 5;
    const int lane = tid & 31;
    const int head = wid >> 1;
    const int qh   = wid & 1;
    const int g    = lane >> 2;
    const int tg   = lane & 3;
    const int lr   = lane & 7;

    const int b  = blockIdx.y;
    const int q0 = blockIdx.x * TQ;

    const float SCALE = 0.03608439182435161f;   // 1/sqrt(768)

    uint32_t qfh[4][4], qfl[4][4];
    {
        const int qrow = (b * SEQ + q0 + qh * 16 + g) * DIMN + head * HD;
#pragma unroll
        for (int c = 0; c < 4; c++) {
            int c0 = 2 * tg + 16 * c;
            qfh[c][0] = *(const uint32_t*)(g_Qh + qrow + c0);
            qfh[c][1] = *(const uint32_t*)(g_Qh + qrow + 8 * DIMN + c0);
            qfh[c][2] = *(const uint32_t*)(g_Qh + qrow + c0 + 8);
            qfh[c][3] = *(const uint32_t*)(g_Qh + qrow + 8 * DIMN + c0 + 8);
            qfl[c][0] = *(const uint32_t*)(g_Ql + qrow + c0);
            qfl[c][1] = *(const uint32_t*)(g_Ql + qrow + 8 * DIMN + c0);
            qfl[c][2] = *(const uint32_t*)(g_Ql + qrow + c0 + 8);
            qfl[c][3] = *(const uint32_t*)(g_Ql + qrow + 8 * DIMN + c0 + 8);
        }
    }

    float o[8][4];
#pragma unroll
    for (int j = 0; j < 8; j++)
#pragma unroll
        for (int r = 0; r < 4; r++) o[j][r] = 0.0f;

    const int kko_k = lr + ((lane >> 4) << 3);
    const int dof_k = ((lane >> 3) & 1) << 3;
    const int kko_v = lr + (((lane >> 3) & 1) << 3);
    const int dof_v = (lane >> 4) << 3;

    const size_t kvbase = (size_t)b * SEQ * DIMN;

    auto load_tile = [&](__nv_bfloat16* dh, __nv_bfloat16* dl,
                         const __nv_bfloat16* gh, const __nv_bfloat16* gl,
                         int kt) {
        const size_t gb = kvbase + (size_t)kt * DIMN;
#pragma unroll
        for (int i = 0; i < 4; i++) {
            int s  = tid + 768 * i;
            int r  = s / 96;
            int cc = (s % 96) * 8;
            cp16(smem_u32(dh + r * KSTR + cc), gh + gb + (size_t)r * DIMN + cc);
            cp16(smem_u32(dl + r * KSTR + cc), gl + gb + (size_t)r * DIMN + cc);
        }
    };

    load_tile(sKh, sKl, g_Kh, g_Kl, 0); cp_commit();
    load_tile(sVh, sVl, g_Vh, g_Vl, 0); cp_commit();
    cp_wait<1>();
    __syncthreads();

    float* Pq = sP + (head * 32 + qh * 16) * PST;
    float s4[4][4];

#pragma unroll 1
    for (int kt = 0; kt < SEQ; kt += TK) {
        const bool has_next = (kt + TK) < SEQ;

#pragma unroll
        for (int j = 0; j < 4; j++)
#pragma unroll
            for (int r = 0; r < 4; r++) s4[j][r] = 0.0f;

#pragma unroll
        for (int p = 0; p < 2; p++) {
#pragma unroll
            for (int c = 0; c < 4; c++) {
                int e = (16 * p + kko_k) * KSTR + head * HD + 16 * c + dof_k;
                uint32_t kh[4], kl[4];
                ldm_x4(kh, smem_u32(sKh + e));
                ldm_x4(kl, smem_u32(sKl + e));
                mma_bf16(s4[2 * p],     qfh[c], kh[0], kh[1]);
                mma_bf16(s4[2 * p],     qfl[c], kh[0], kh[1]);
                mma_bf16(s4[2 * p],     qfh[c], kl[0], kl[1]);
                mma_bf16(s4[2 * p + 1], qfh[c], kh[2], kh[3]);
                mma_bf16(s4[2 * p + 1], qfl[c], kh[2], kh[3]);
                mma_bf16(s4[2 * p + 1], qfh[c], kl[2], kl[3]);
            }
        }

#pragma unroll
        for (int j = 0; j < 4; j++)
#pragma unroll
            for (int r = 0; r < 4; r++) s4[j][r] = fast_exp(s4[j][r]);

#pragma unroll
        for (int j = 0; j < 2; j++) {
            *(float2*)(Pq + g * PST + 8 * j + 2 * tg)       = make_float2(s4[j][0], s4[j][1]);
            *(float2*)(Pq + (g + 8) * PST + 8 * j + 2 * tg) = make_float2(s4[j][2], s4[j][3]);
        }
        __syncthreads();
        if (has_next) load_tile(sKh, sKl, g_Kh, g_Kl, kt + TK);
        cp_commit();

        if (tid < 512) {
            int q = tid >> 4, k = tid & 15;
            float den = 0.0f;
#pragma unroll
            for (int h = 0; h < NH; h++) den += sP[(h * 32 + q) * PST + k];
            sI[q * PST + k] = __fdividef(SCALE, den);
        }
        __syncthreads();

#pragma unroll
        for (int j = 2; j < 4; j++) {
            *(float2*)(Pq + g * PST + 8 * (j - 2) + 2 * tg)       = make_float2(s4[j][0], s4[j][1]);
            *(float2*)(Pq + (g + 8) * PST + 8 * (j - 2) + 2 * tg) = make_float2(s4[j][2], s4[j][3]);
        }
        __syncthreads();

        if (tid < 512) {
            int q = tid >> 4, k = tid & 15;
            float den = 0.0f;
#pragma unroll
            for (int h = 0; h < NH; h++) den += sP[(h * 32 + q) * PST + k];
            sI[32 * PST + q * PST + k] = __fdividef(SCALE, den);
        }
        if (has_next) cp_wait<1>(); else cp_wait<0>();
        __syncthreads();

        uint32_t ph[2][4], pl[2][4];
        {
            const int qr = qh * 16 + g;
#pragma unroll
            for (int c = 0; c < 2; c++) {
                const float* invh = sI + c * (32 * PST);
#pragma unroll
                for (int hf = 0; hf < 2; hf++) {
                    const float* ir = invh + (qr + 8 * hf) * PST + 2 * tg;
                    float2 iv0 = *(const float2*)(ir);
                    float2 iv1 = *(const float2*)(ir + 8);
                    float p0 = s4[2 * c][2 * hf]     * iv0.x;
                    float p1 = s4[2 * c][2 * hf + 1] * iv0.y;
                    float p2 = s4[2 * c + 1][2 * hf]     * iv1.x;
                    float p3 = s4[2 * c + 1][2 * hf + 1] * iv1.y;
                    uint32_t h0 = packbf(p0, p1);
                    uint32_t h1 = packbf(p2, p3);
                    __nv_bfloat162 b0 = *(__nv_bfloat162*)&h0;
                    __nv_bfloat162 b1 = *(__nv_bfloat162*)&h1;
                    ph[c][hf]     = h0;
                    ph[c][2 + hf] = h1;
                    pl[c][hf]     = packbf(p0 - __bfloat162float(b0.x),
                                           p1 - __bfloat162float(b0.y));
                    pl[c][2 + hf] = packbf(p2 - __bfloat162float(b1.x),
                                           p3 - __bfloat162float(b1.y));
                }
            }
        }

#pragma unroll
        for (int c = 0; c < 2; c++) {
#pragma unroll
            for (int dp = 0; dp < 4; dp++) {
                int e = (16 * c + kko_v) * KSTR + head * HD + 16 * dp + dof_v;
                uint32_t vh[4], vl[4];
                ldm_x4_t(vh, smem_u32(sVh + e));
                ldm_x4_t(vl, smem_u32(sVl + e));
                mma_bf16(o[2 * dp],     ph[c], vh[0], vh[1]);
                mma_bf16(o[2 * dp],     pl[c], vh[0], vh[1]);
                mma_bf16(o[2 * dp],     ph[c], vl[0], vl[1]);
                mma_bf16(o[2 * dp + 1], ph[c], vh[2], vh[3]);
                mma_bf16(o[2 * dp + 1], pl[c], vh[2], vh[3]);
                mma_bf16(o[2 * dp + 1], ph[c], vl[2], vl[3]);
            }
        }

        cp_wait<0>();
        __syncthreads();
        if (has_next) load_tile(sVh, sVl, g_Vh, g_Vl, kt + TK);
        cp_commit();
    }

    float* Ob = Out + (size_t)(b * SEQ + q0 + qh * 16) * DIMN + head * HD;
#pragma unroll
    for (int j = 0; j < 8; j++) {
        int d = 8 * j + 2 * tg;
        *(float2*)(Ob + (size_t)g * DIMN + d)       = make_float2(o[j][0], o[j][1]);
        *(float2*)(Ob + (size_t)(g + 8) * DIMN + d) = make_float2(o[j][2], o[j][3]);
    }
}

// ---------------------------------------------------------------------------
extern "C" void kernel_launch(void* const* d_in, const int* in_sizes, int n_in,
                              void* d_out, int out_size)
{
    const float* x  = (const float*)d_in[0];
    const float* Wq = (const float*)d_in[1];
    const float* Wk = (const float*)d_in[2];
    const float* Wv = (const float*)d_in[3];
    float* out = (float*)d_out;

    // split inputs into bf16 hi/lo (destinations resolved in device code)
    {
        int n4x = 4096 * DIMN / 4;
        cvt_split<<<(n4x + 255) / 256, 256>>>(x, 0, 0, n4x);
        int n4w = DIMN * DIMN / 4;
        cvt_split<<<(n4w + 255) / 256, 256>>>(Wq, 1, 0, n4w);
        cvt_split<<<(n4w + 255) / 256, 256>>>(Wk, 1, DIMN * DIMN, n4w);
        cvt_split<<<(n4w + 255) / 256, 256>>>(Wv, 1, 2 * DIMN * DIMN, n4w);
    }

    cudaFuncSetAttribute(qkv_mma, cudaFuncAttributeMaxDynamicSharedMemorySize, Q_SMEM);
    dim3 g1(4096 / 128, DIMN / 128, 3);
    qkv_mma<<<g1, 256, Q_SMEM>>>();

    cudaFuncSetAttribute(attn_kernel, cudaFuncAttributeMaxDynamicSharedMemorySize, SMEM_TOTAL);
    dim3 g2(SEQ / TQ, BATCH);
    attn_kernel<<<g2, 768, SMEM_TOTAL>>>(out);
}